// round 16
// baseline (speedup 1.0000x reference)
#include <cuda_runtime.h>
#include <cuda_fp16.h>
#include <math.h>

#define QLEN  1024
#define BATCH 4
#define DMODEL 1024
#define NH    16
#define HD    64
#define MEMLEN 512
#define KLEN  1536
#define MLPD  4096
#define QKV3  3072
#define ATT_SCALE 0.125f
#define LNEPS 1e-5f

// ---------------- scratch (static device globals; no allocation) ----------------
__device__ __half g_cat_h [(size_t)KLEN * BATCH * DMODEL];
__device__ __half g_qkv_h [(size_t)KLEN * BATCH * QKV3];
__device__ __half g_rp_h  [(size_t)KLEN * DMODEL];
__device__ __half g_BD    [(size_t)BATCH * NH * QLEN * KLEN];
__device__ __half g_ctx_h [(size_t)QLEN * BATCH * DMODEL];
__device__ float  g_y     [(size_t)QLEN * BATCH * DMODEL];
__device__ float  g_x     [(size_t)QLEN * BATCH * DMODEL];
__device__ __half g_x_h   [(size_t)QLEN * BATCH * DMODEL];
__device__ __half g_h_h   [(size_t)QLEN * BATCH * MLPD];
__device__ float  g_y2    [(size_t)QLEN * BATCH * DMODEL];
__device__ __half g_wqkv_h[(size_t)DMODEL * QKV3];
__device__ __half g_wr_h  [(size_t)DMODEL * DMODEL];
__device__ __half g_wo_h  [(size_t)DMODEL * DMODEL];
__device__ __half g_w1_h  [(size_t)DMODEL * MLPD];
__device__ __half g_w2_h  [(size_t)MLPD * DMODEL];
__device__ __half g_r_h   [(size_t)KLEN * DMODEL];

// ---------------- helpers ----------------
__device__ __forceinline__ unsigned pk(float a, float b) {
    __half2 h = __floats2half2_rn(a, b);
    return *(unsigned*)&h;
}
__device__ __forceinline__ void mma16(float c[4],
    unsigned a0, unsigned a1, unsigned a2, unsigned a3, unsigned b0, unsigned b1) {
    asm volatile(
        "mma.sync.aligned.m16n8k16.row.col.f32.f16.f16.f32 "
        "{%0,%1,%2,%3},{%4,%5,%6,%7},{%8,%9},{%0,%1,%2,%3};"
        : "+f"(c[0]), "+f"(c[1]), "+f"(c[2]), "+f"(c[3])
        : "r"(a0), "r"(a1), "r"(a2), "r"(a3), "r"(b0), "r"(b1));
}
__device__ __forceinline__ void ldm4(unsigned &r0, unsigned &r1, unsigned &r2, unsigned &r3,
                                     unsigned addr) {
    asm volatile("ldmatrix.sync.aligned.m8n8.x4.shared.b16 {%0,%1,%2,%3}, [%4];"
        : "=r"(r0), "=r"(r1), "=r"(r2), "=r"(r3) : "r"(addr));
}
__device__ __forceinline__ void ldm4t(unsigned &r0, unsigned &r1, unsigned &r2, unsigned &r3,
                                      unsigned addr) {
    asm volatile("ldmatrix.sync.aligned.m8n8.x4.trans.shared.b16 {%0,%1,%2,%3}, [%4];"
        : "=r"(r0), "=r"(r1), "=r"(r2), "=r"(r3) : "r"(addr));
}
#define CPA(dst, src) asm volatile("cp.async.cg.shared.global [%0],[%1],16;\n" :: "r"(dst), "l"(src))
#define CPC()         asm volatile("cp.async.commit_group;\n")
#define CPW(n)        asm volatile("cp.async.wait_group %0;\n" :: "n"(n))

// ---------------- fused rounding to fp16: weights + r + concat in ONE launch --------
struct Seg { const float* s; __half* d; size_t n4; };
struct Segs8 { Seg v[8]; };
__global__ void round_all(Segs8 segs) {
    #pragma unroll 1
    for (int k = 0; k < 8; k++) {
        const float* s = segs.v[k].s;
        __half* d = segs.v[k].d;
        size_t n4 = segs.v[k].n4;
        for (size_t i = (size_t)blockIdx.x * blockDim.x + threadIdx.x; i < n4;
             i += (size_t)gridDim.x * blockDim.x) {
            float4 v = ((const float4*)s)[i];
            uint2 t = { pk(v.x, v.y), pk(v.z, v.w) };
            ((uint2*)d)[i] = t;
        }
    }
}

// ---------------- 2-stage cp.async fp16 GEMM, block 128x128, BK=32 ------------------
// C = A[M,K] @ B[K,N] (+bias)(+relu); A row-major, B row-major (ldmatrix.trans)
#define GAH 40
#define GBH 136
__global__ __launch_bounds__(256, 2) void gemm_h(
    const __half* __restrict__ A, const __half* __restrict__ B,
    float* __restrict__ Cf, __half* __restrict__ Ch,
    const float* __restrict__ bias, int M, int N, int K, int relu, int qkvskip)
{
    extern __shared__ __half smh[];
    __half* As = smh;                      // [2][128*GAH]
    __half* Bs = smh + 2 * 128 * GAH;      // [2][32*GBH]
    unsigned sA = (unsigned)__cvta_generic_to_shared(As);
    unsigned sB = (unsigned)__cvta_generic_to_shared(Bs);
    int tid = threadIdx.x, lane = tid & 31, warp = tid >> 5;
    int qid = lane >> 2, qt = lane & 3;
    int l15 = lane & 15, lh = (lane >> 4) << 3;
    int wm = (warp >> 2) * 64, wn = (warp & 3) * 32;
    int m0 = blockIdx.y * 128, n0 = blockIdx.x * 128;
    if (qkvskip && (m0 + 128 <= MEMLEN * BATCH) && (n0 < DMODEL)) return;

    float c[4][4][4];
    #pragma unroll
    for (int mi = 0; mi < 4; mi++)
        #pragma unroll
        for (int ni = 0; ni < 4; ni++)
            #pragma unroll
            for (int t = 0; t < 4; t++) c[mi][ni][t] = 0.0f;

    auto stage_load = [&](int kt, int s) {
        int kb = kt << 5;
        #pragma unroll
        for (int i = 0; i < 2; i++) {               // A: 128 x 32 halves
            int id = tid + i * 256; int r = id >> 2, cc = (id & 3) * 8;
            CPA(sA + (s * 128 * GAH + r * GAH + cc) * 2, A + (size_t)(m0 + r) * K + kb + cc);
        }
        #pragma unroll
        for (int i = 0; i < 2; i++) {               // B: 32 x 128 halves
            int id = tid + i * 256; int r = id >> 4, cc = (id & 15) * 8;
            CPA(sB + (s * 32 * GBH + r * GBH + cc) * 2, B + (size_t)(kb + r) * N + n0 + cc);
        }
    };

    int KT = K >> 5;
    stage_load(0, 0); CPC();
    for (int kt = 0; kt < KT; kt++) {
        int s = kt & 1;
        if (kt + 1 < KT) stage_load(kt + 1, s ^ 1);
        CPC();
        CPW(1);
        __syncthreads();
        unsigned aoff = sA + (s * 128 * GAH) * 2;
        unsigned boff = sB + (s * 32 * GBH) * 2;
        #pragma unroll
        for (int kk = 0; kk < 2; kk++) {
            unsigned a[4][4], bf[4][2];
            #pragma unroll
            for (int mi = 0; mi < 4; mi++)
                ldm4(a[mi][0], a[mi][1], a[mi][2], a[mi][3],
                     aoff + (unsigned)(((wm + mi * 16 + l15) * GAH + kk * 16 + lh) * 2));
            #pragma unroll
            for (int nh = 0; nh < 2; nh++) {
                unsigned r0, r1, r2, r3;
                ldm4t(r0, r1, r2, r3,
                      boff + (unsigned)(((kk * 16 + l15) * GBH + wn + nh * 16 + lh) * 2));
                bf[nh * 2][0] = r0; bf[nh * 2][1] = r1;
                bf[nh * 2 + 1][0] = r2; bf[nh * 2 + 1][1] = r3;
            }
            #pragma unroll
            for (int mi = 0; mi < 4; mi++)
                #pragma unroll
                for (int ni = 0; ni < 4; ni++)
                    mma16(c[mi][ni], a[mi][0], a[mi][1], a[mi][2], a[mi][3],
                          bf[ni][0], bf[ni][1]);
        }
        __syncthreads();
    }
    #pragma unroll
    for (int mi = 0; mi < 4; mi++) {
        int row = m0 + wm + mi * 16 + qid;
        #pragma unroll
        for (int ni = 0; ni < 4; ni++) {
            int col = n0 + wn + ni * 8 + qt * 2;
            float b0 = bias ? bias[col] : 0.0f;
            float b1 = bias ? bias[col + 1] : 0.0f;
            float v00 = c[mi][ni][0] + b0, v01 = c[mi][ni][1] + b1;
            float v10 = c[mi][ni][2] + b0, v11 = c[mi][ni][3] + b1;
            if (relu) { v00 = fmaxf(v00, 0.f); v01 = fmaxf(v01, 0.f);
                        v10 = fmaxf(v10, 0.f); v11 = fmaxf(v11, 0.f); }
            if (Ch) {
                *(__half2*)(Ch + (size_t)row * N + col)       = __floats2half2_rn(v00, v01);
                *(__half2*)(Ch + (size_t)(row + 8) * N + col) = __floats2half2_rn(v10, v11);
            } else {
                Cf[(size_t)row * N + col]           = v00;
                Cf[(size_t)row * N + col + 1]       = v01;
                Cf[(size_t)(row + 8) * N + col]     = v10;
                Cf[(size_t)(row + 8) * N + col + 1] = v11;
            }
        }
    }
}

// ---------------- BD kernel: pre-shifted scaled BD (fp16, v-add fused) --------------
// Epilogue: stage S tile in smem (reusing Q/R buffers), then per-row COALESCED stores.
#define BDH 72
#define BSS 136
__global__ __launch_bounds__(256) void bd_h(
    const __half* __restrict__ qkv, const __half* __restrict__ rp,
    const float* __restrict__ vvec, __half* __restrict__ BDs)
{
    int i0 = blockIdx.y * 128, j0 = blockIdx.x * 128;
    if (j0 + i0 <= QLEN - 256) return;   // all stored j < 0: tile dead
    extern __shared__ __half smh[];
    __half* Qs = smh;                  // [128][BDH]
    __half* Rs = smh + 128 * BDH;      // [128][BDH]
    unsigned sQ = (unsigned)__cvta_generic_to_shared(Qs);
    unsigned sR = (unsigned)__cvta_generic_to_shared(Rs);
    int tid = threadIdx.x, lane = tid & 31, warp = tid >> 5;
    int qid = lane >> 2, qt = lane & 3;
    int l15 = lane & 15, lh = (lane >> 4) << 3;
    int wm = (warp >> 2) * 64, wn = (warp & 3) * 32;
    int bh = blockIdx.z, b = bh >> 4, h = bh & 15;

    #pragma unroll
    for (int i = 0; i < 4; i++) {
        int id = tid + i * 256; int r = id >> 3, cc = (id & 7) * 8;
        uint4 q = *(const uint4*)(qkv + ((size_t)(MEMLEN + i0 + r) * BATCH + b) * QKV3 + h * 64 + cc);
        __half2* qh = (__half2*)&q;
        float4 va = *(const float4*)(vvec + h * 64 + cc);
        float4 vb = *(const float4*)(vvec + h * 64 + cc + 4);
        uint4 t;
        t.x = pk(__low2float(qh[0]) + va.x, __high2float(qh[0]) + va.y);
        t.y = pk(__low2float(qh[1]) + va.z, __high2float(qh[1]) + va.w);
        t.z = pk(__low2float(qh[2]) + vb.x, __high2float(qh[2]) + vb.y);
        t.w = pk(__low2float(qh[3]) + vb.z, __high2float(qh[3]) + vb.w);
        *(uint4*)&Qs[r * BDH + cc] = t;
        *(uint4*)&Rs[r * BDH + cc] =
            *(const uint4*)(rp + (size_t)(j0 + r) * DMODEL + h * 64 + cc);
    }
    __syncthreads();
    float c[4][4][4];
    #pragma unroll
    for (int mi = 0; mi < 4; mi++)
        #pragma unroll
        for (int ni = 0; ni < 4; ni++)
            #pragma unroll
            for (int t = 0; t < 4; t++) c[mi][ni][t] = 0.0f;
    #pragma unroll
    for (int kc = 0; kc < 4; kc++) {
        unsigned a[4][4], bf[4][2];
        #pragma unroll
        for (int mi = 0; mi < 4; mi++)
            ldm4(a[mi][0], a[mi][1], a[mi][2], a[mi][3],
                 sQ + (unsigned)(((wm + mi * 16 + l15) * BDH + kc * 16 + lh) * 2));
        #pragma unroll
        for (int nh = 0; nh < 2; nh++) {
            unsigned r0, r1, r2, r3;
            ldm4(r0, r1, r2, r3,
                 sR + (unsigned)(((wn + nh * 16 + l15) * BDH + kc * 16 + lh) * 2));
            bf[nh * 2][0] = r0; bf[nh * 2][1] = r2;        // non-trans: interleaved
            bf[nh * 2 + 1][0] = r1; bf[nh * 2 + 1][1] = r3;
        }
        #pragma unroll
        for (int mi = 0; mi < 4; mi++)
            #pragma unroll
            for (int ni = 0; ni < 4; ni++)
                mma16(c[mi][ni], a[mi][0], a[mi][1], a[mi][2], a[mi][3],
                      bf[ni][0], bf[ni][1]);
    }
    // stage scaled S into smem (reuse Qs/Rs region: 128 x BSS halves = 34.8 KB <= 36.8 KB)
    __syncthreads();
    __half* Ss = smh;
    #pragma unroll
    for (int mi = 0; mi < 4; mi++) {
        #pragma unroll
        for (int half = 0; half < 2; half++) {
            int rloc = wm + mi * 16 + qid + half * 8;
            #pragma unroll
            for (int ni = 0; ni < 4; ni++) {
                int col = wn + ni * 8 + qt * 2;
                *(__half2*)&Ss[rloc * BSS + col] =
                    __floats2half2_rn(c[mi][ni][half * 2]     * ATT_SCALE,
                                      c[mi][ni][half * 2 + 1] * ATT_SCALE);
            }
        }
    }
    __syncthreads();
    // coalesced write-out: warp w owns rows [w*16, w*16+16)
    __half* bdp = BDs + (size_t)bh * QLEN * KLEN;
    #pragma unroll 1
    for (int rr = 0; rr < 16; rr++) {
        int r = warp * 16 + rr;
        int i = i0 + r;
        int jb = j0 - (QLEN - 1) + i;
        int lo = jb < 0 ? -jb : 0;
        int hi = KLEN - jb; if (hi > 128) hi = 128;
        __half* dst = bdp + (size_t)i * KLEN + jb;
        for (int cpos = lo + lane; cpos < hi; cpos += 32)
            dst[cpos] = Ss[r * BSS + cpos];
    }
}

// ---------------- fused flash attention (fp16 mma, P in registers) ------------------
#define FH 72
__global__ __launch_bounds__(256) void flash_attn(
    const __half* __restrict__ qkv, const float* __restrict__ uvec,
    const __half* __restrict__ BDs, __half* __restrict__ ctx)
{
    extern __shared__ __half smh[];
    __half* Qs = smh;                      // [128][FH]
    __half* Ks = Qs + 128 * FH;            // [2][64][FH]
    __half* Vs = Ks + 2 * 64 * FH;         // [2][64][FH]
    unsigned sQ = (unsigned)__cvta_generic_to_shared(Qs);
    unsigned sK = (unsigned)__cvta_generic_to_shared(Ks);
    unsigned sV = (unsigned)__cvta_generic_to_shared(Vs);

    int tid = threadIdx.x, lane = tid & 31, warp = tid >> 5;
    int qid = lane >> 2, qt = lane & 3;
    int l15 = lane & 15, lh = (lane >> 4) << 3;
    int bh = blockIdx.y, b = bh >> 4, h = bh & 15;
    int i0 = blockIdx.x * 128;
    int r0w = warp * 16;

    // Q tile (u-add fused)
    #pragma unroll
    for (int i = 0; i < 4; i++) {
        int id = tid + i * 256; int r = id >> 3, cc = (id & 7) * 8;
        uint4 q = *(const uint4*)(qkv + ((size_t)(MEMLEN + i0 + r) * BATCH + b) * QKV3 + h * 64 + cc);
        __half2* qh = (__half2*)&q;
        float4 ua = *(const float4*)(uvec + h * 64 + cc);
        float4 ub = *(const float4*)(uvec + h * 64 + cc + 4);
        uint4 t;
        t.x = pk(__low2float(qh[0]) + ua.x, __high2float(qh[0]) + ua.y);
        t.y = pk(__low2float(qh[1]) + ua.z, __high2float(qh[1]) + ua.w);
        t.z = pk(__low2float(qh[2]) + ub.x, __high2float(qh[2]) + ub.y);
        t.w = pk(__low2float(qh[3]) + ub.z, __high2float(qh[3]) + ub.w);
        *(uint4*)&Qs[r * FH + cc] = t;
    }

    int njt = i0 / 64 + 10;
    if (njt > KLEN / 64) njt = KLEN / 64;

    auto stage = [&](int jt, int bf) {
        int j0 = jt * 64;
        #pragma unroll
        for (int i = 0; i < 2; i++) {
            int id = tid + i * 256; int r = id >> 3, cc = (id & 7) * 8;
            const __half* kg = qkv + ((size_t)(j0 + r) * BATCH + b) * QKV3 + DMODEL + h * 64 + cc;
            CPA(sK + ((bf * 64 + r) * FH + cc) * 2, kg);
            CPA(sV + ((bf * 64 + r) * FH + cc) * 2, kg + DMODEL);
        }
    };

    stage(0, 0); CPC();

    float m0 = -1e30f, m1 = -1e30f, l0 = 0.0f, l1 = 0.0f;
    float o[8][4];
    #pragma unroll
    for (int nt = 0; nt < 8; nt++)
        #pragma unroll
        for (int t = 0; t < 4; t++) o[nt][t] = 0.0f;

    const __half* bdp = BDs + ((size_t)bh * QLEN + i0) * KLEN;
    int irow0 = i0 + r0w + qid, irow1 = irow0 + 8;

    for (int jt = 0; jt < njt; jt++) {
        int buf = jt & 1;
        int j0 = jt * 64;
        if (jt + 1 < njt) stage(jt + 1, buf ^ 1);
        CPC();
        CPW(1);
        __syncthreads();
        unsigned sKb = sK + buf * 64 * FH * 2;
        unsigned sVb = sV + buf * 64 * FH * 2;

        // S = Q K^T
        float s[8][4];
        #pragma unroll
        for (int nt = 0; nt < 8; nt++)
            #pragma unroll
            for (int t = 0; t < 4; t++) s[nt][t] = 0.0f;
        #pragma unroll
        for (int kc = 0; kc < 4; kc++) {
            unsigned a0, a1, a2, a3;
            ldm4(a0, a1, a2, a3,
                 sQ + (unsigned)(((r0w + l15) * FH + kc * 16 + lh) * 2));
            #pragma unroll
            for (int jb = 0; jb < 4; jb++) {
                unsigned r0, r1, r2, r3;
                ldm4(r0, r1, r2, r3,
                     sKb + (unsigned)(((jb * 16 + l15) * FH + kc * 16 + lh) * 2));
                mma16(s[jb * 2],     a0, a1, a2, a3, r0, r2);
                mma16(s[jb * 2 + 1], a0, a1, a2, a3, r1, r3);
            }
        }

        // scores: scale + BD (half2 loads) + mask; warp-local online softmax
        int msk = (j0 + 63 > i0 + MEMLEN);
        float mx0 = -1e30f, mx1 = -1e30f;
        #pragma unroll
        for (int nt = 0; nt < 8; nt++) {
            int k0 = j0 + nt * 8 + qt * 2, k1 = k0 + 1;
            __half2 bd0 = *(const __half2*)(bdp + (size_t)(r0w + qid) * KLEN + k0);
            __half2 bd1 = *(const __half2*)(bdp + (size_t)(r0w + qid + 8) * KLEN + k0);
            float v0 = s[nt][0] * ATT_SCALE + __low2float(bd0);
            float v1 = s[nt][1] * ATT_SCALE + __high2float(bd0);
            float v2 = s[nt][2] * ATT_SCALE + __low2float(bd1);
            float v3 = s[nt][3] * ATT_SCALE + __high2float(bd1);
            if (msk) {
                if (k0 > irow0 + MEMLEN) v0 = -1e30f;
                if (k1 > irow0 + MEMLEN) v1 = -1e30f;
                if (k0 > irow1 + MEMLEN) v2 = -1e30f;
                if (k1 > irow1 + MEMLEN) v3 = -1e30f;
            }
            s[nt][0] = v0; s[nt][1] = v1; s[nt][2] = v2; s[nt][3] = v3;
            mx0 = fmaxf(mx0, fmaxf(v0, v1));
            mx1 = fmaxf(mx1, fmaxf(v2, v3));
        }
        mx0 = fmaxf(mx0, __shfl_xor_sync(0xffffffffu, mx0, 1));
        mx0 = fmaxf(mx0, __shfl_xor_sync(0xffffffffu, mx0, 2));
        mx1 = fmaxf(mx1, __shfl_xor_sync(0xffffffffu, mx1, 1));
        mx1 = fmaxf(mx1, __shfl_xor_sync(0xffffffffu, mx1, 2));
        float mn0 = fmaxf(m0, mx0), mn1 = fmaxf(m1, mx1);
        float al0 = __expf(m0 - mn0), al1 = __expf(m1 - mn1);
        m0 = mn0; m1 = mn1;
        #pragma unroll
        for (int nt = 0; nt < 8; nt++) {
            o[nt][0] *= al0; o[nt][1] *= al0;
            o[nt][2] *= al1; o[nt][3] *= al1;
        }
        float rs0 = 0.0f, rs1 = 0.0f;
        #pragma unroll
        for (int nt = 0; nt < 8; nt++) {
            s[nt][0] = __expf(s[nt][0] - mn0);
            s[nt][1] = __expf(s[nt][1] - mn0);
            s[nt][2] = __expf(s[nt][2] - mn1);
            s[nt][3] = __expf(s[nt][3] - mn1);
            rs0 += s[nt][0] + s[nt][1];
            rs1 += s[nt][2] + s[nt][3];
        }
        rs0 += __shfl_xor_sync(0xffffffffu, rs0, 1);
        rs0 += __shfl_xor_sync(0xffffffffu, rs0, 2);
        rs1 += __shfl_xor_sync(0xffffffffu, rs1, 1);
        rs1 += __shfl_xor_sync(0xffffffffu, rs1, 2);
        l0 = l0 * al0 + rs0;
        l1 = l1 * al1 + rs1;

        // O += P @ V   (fp16 A-frag packs directly from S C-frags: cols {2t,2t+1})
        #pragma unroll
        for (int c4 = 0; c4 < 4; c4++) {
            unsigned a0 = pk(s[2 * c4][0],     s[2 * c4][1]);
            unsigned a1 = pk(s[2 * c4][2],     s[2 * c4][3]);
            unsigned a2 = pk(s[2 * c4 + 1][0], s[2 * c4 + 1][1]);
            unsigned a3 = pk(s[2 * c4 + 1][2], s[2 * c4 + 1][3]);
            #pragma unroll
            for (int db = 0; db < 4; db++) {
                unsigned r0, r1, r2, r3;
                ldm4t(r0, r1, r2, r3,
                      sVb + (unsigned)(((c4 * 16 + l15) * FH + db * 16 + lh) * 2));
                mma16(o[db * 2],     a0, a1, a2, a3, r0, r1);
                mma16(o[db * 2 + 1], a0, a1, a2, a3, r2, r3);
            }
        }
        __syncthreads();
    }

    // epilogue: O /= l, fp16 ctx
    float inv0 = 1.0f / l0, inv1 = 1.0f / l1;
    int row0 = i0 + r0w + qid;
    #pragma unroll
    for (int nt = 0; nt < 8; nt++) {
        int col = h * 64 + nt * 8 + qt * 2;
        *(__half2*)(ctx + ((size_t)row0 * BATCH + b) * DMODEL + col) =
            __floats2half2_rn(o[nt][0] * inv0, o[nt][1] * inv0);
        *(__half2*)(ctx + ((size_t)(row0 + 8) * BATCH + b) * DMODEL + col) =
            __floats2half2_rn(o[nt][2] * inv1, o[nt][3] * inv1);
    }
}

// ---------------- layernorm: out = LN(a + b) * g + beta (+ optional fp16 copy) ------
__global__ __launch_bounds__(256) void ln_kernel(
    const float* __restrict__ a, const float* __restrict__ bres,
    const float* __restrict__ g, const float* __restrict__ beta,
    float* __restrict__ out, __half* __restrict__ out_h)
{
    int row = blockIdx.x;
    int tid = threadIdx.x;
    const float* ap = a    + (size_t)row * DMODEL;
    const float* bp = bres + (size_t)row * DMODEL;
    float x[4];
    float sum = 0.0f;
    #pragma unroll
    for (int t = 0; t < 4; t++) {
        int c = tid + t * 256;
        x[t] = ap[c] + bp[c];
        sum += x[t];
    }
    __shared__ float red[256];
    red[tid] = sum; __syncthreads();
    for (int o = 128; o > 0; o >>= 1) {
        if (tid < o) red[tid] += red[tid + o];
        __syncthreads();
    }
    float mean = red[0] * (1.0f / DMODEL); __syncthreads();
    float vs = 0.0f;
    #pragma unroll
    for (int t = 0; t < 4; t++) { float d = x[t] - mean; vs += d * d; }
    red[tid] = vs; __syncthreads();
    for (int o = 128; o > 0; o >>= 1) {
        if (tid < o) red[tid] += red[tid + o];
        __syncthreads();
    }
    float inv = rsqrtf(red[0] * (1.0f / DMODEL) + LNEPS);
    #pragma unroll
    for (int t = 0; t < 4; t++) {
        int c = tid + t * 256;
        float v = (x[t] - mean) * inv * g[c] + beta[c];
        out[(size_t)row * DMODEL + c] = v;
        if (out_h) out_h[(size_t)row * DMODEL + c] = __float2half(v);
    }
}

// ---------------- launch ----------------
extern "C" void kernel_launch(void* const* d_in, const int* in_sizes, int n_in,
                              void* d_out, int out_size)
{
    const float* inputs = (const float*)d_in[0];
    const float* r      = (const float*)d_in[1];
    const float* u      = (const float*)d_in[2];
    const float* v      = (const float*)d_in[3];
    const float* mem    = (const float*)d_in[4];
    const float* W_qkv  = (const float*)d_in[6];
    const float* W_r    = (const float*)d_in[7];
    const float* W_o    = (const float*)d_in[8];
    const float* ln1_g  = (const float*)d_in[9];
    const float* ln1_b  = (const float*)d_in[10];
    const float* ln2_g  = (const float*)d_in[11];
    const float* ln2_b  = (const float*)d_in[12];
    const float* W1     = (const float*)d_in[13];
    const float* b1     = (const float*)d_in[14];
    const float* W2     = (const float*)d_in[15];
    const float* b2     = (const float*)d_in[16];
    float* out = (float*)d_out;

    __half *cat_h, *qkv_h, *rp_h, *ctx_h, *x_h, *h_h, *BDs;
    __half *wqkv_h, *wr_h, *wo_h, *w1_h, *w2_h, *r_h;
    float *y, *x, *y2;
    cudaGetSymbolAddress((void**)&cat_h,  g_cat_h);
    cudaGetSymbolAddress((void**)&qkv_h,  g_qkv_h);
    cudaGetSymbolAddress((void**)&rp_h,   g_rp_h);
    cudaGetSymbolAddress((void**)&BDs,    g_BD);
    cudaGetSymbolAddress((void**)&ctx_h,  g_ctx_h);
    cudaGetSymbolAddress((void**)&y,      g_y);
    cudaGetSymbolAddress((void**)&x,      g_x);
    cudaGetSymbolAddress((void**)&x_h,    g_x_h);
    cudaGetSymbolAddress((void**)&h_h,    g_h_h);
    cudaGetSymbolAddress((void**)&y2,     g_y2);
    cudaGetSymbolAddress((void**)&wqkv_h, g_wqkv_h);
    cudaGetSymbolAddress((void**)&wr_h,   g_wr_h);
    cudaGetSymbolAddress((void**)&wo_h,   g_wo_h);
    cudaGetSymbolAddress((void**)&w1_h,   g_w1_h);
    cudaGetSymbolAddress((void**)&w2_h,   g_w2_h);
    cudaGetSymbolAddress((void**)&r_h,    g_r_h);

    const int gemm_smem  = (2 * 128 * GAH + 2 * 32 * GBH) * 2;
    const int bd_smem    = (2 * 128 * BDH) * 2;
    const int flash_smem = (128 * FH + 4 * 64 * FH) * 2;
    cudaFuncSetAttribute(gemm_h,     cudaFuncAttributeMaxDynamicSharedMemorySize, gemm_smem);
    cudaFuncSetAttribute(bd_h,       cudaFuncAttributeMaxDynamicSharedMemorySize, bd_smem);
    cudaFuncSetAttribute(flash_attn, cudaFuncAttributeMaxDynamicSharedMemorySize, flash_smem);

    // 0. one fused rounding launch: weights, r, and concat([mem; inputs]) -> fp16
    Segs8 segs;
    segs.v[0] = { W_qkv, wqkv_h, (size_t)DMODEL * QKV3 / 4 };
    segs.v[1] = { W1,    w1_h,   (size_t)DMODEL * MLPD / 4 };
    segs.v[2] = { W2,    w2_h,   (size_t)MLPD * DMODEL / 4 };
    segs.v[3] = { W_r,   wr_h,   (size_t)DMODEL * DMODEL / 4 };
    segs.v[4] = { W_o,   wo_h,   (size_t)DMODEL * DMODEL / 4 };
    segs.v[5] = { r,     r_h,    (size_t)KLEN * DMODEL / 4 };
    segs.v[6] = { mem,   cat_h,  (size_t)MEMLEN * BATCH * DMODEL / 4 };
    segs.v[7] = { inputs, cat_h + (size_t)MEMLEN * BATCH * DMODEL,
                  (size_t)QLEN * BATCH * DMODEL / 4 };
    round_all<<<2048, 256>>>(segs);

    // 1. qkv_h = cat_h @ W_qkv (fp16 out; Q-third skipped for mem rows)
    gemm_h<<<dim3(QKV3 / 128, (KLEN * BATCH) / 128), 256, gemm_smem>>>(
        cat_h, wqkv_h, nullptr, qkv_h, nullptr, KLEN * BATCH, QKV3, DMODEL, 0, 1);

    // 2. rp_h = r @ W_r (fp16 out)
    gemm_h<<<dim3(DMODEL / 128, KLEN / 128), 256, gemm_smem>>>(
        r_h, wr_h, nullptr, rp_h, nullptr, KLEN, DMODEL, DMODEL, 0, 0);

    // 3. BDs (pre-shifted, pre-scaled fp16; v-add fused; coalesced store)
    bd_h<<<dim3(KLEN / 128, QLEN / 128, BATCH * NH), 256, bd_smem>>>(qkv_h, rp_h, v, BDs);

    // 4. fused flash attention -> ctx_h (u-add fused)
    flash_attn<<<dim3(QLEN / 128, BATCH * NH), 256, flash_smem>>>(qkv_h, u, BDs, ctx_h);

    // 5. y = ctx_h @ W_o (fp32 out)
    gemm_h<<<dim3(DMODEL / 128, (QLEN * BATCH) / 128), 256, gemm_smem>>>(
        ctx_h, wo_h, y, nullptr, nullptr, QLEN * BATCH, DMODEL, DMODEL, 0, 0);

    // 6. x = LN1(inputs + y)  (+ fp16 copy)
    ln_kernel<<<QLEN * BATCH, 256>>>(inputs, y, ln1_g, ln1_b, x, x_h);

    // 7. h_h = relu(x_h @ W1 + b1) (fp16 out)
    gemm_h<<<dim3(MLPD / 128, (QLEN * BATCH) / 128), 256, gemm_smem>>>(
        x_h, w1_h, nullptr, h_h, b1, QLEN * BATCH, MLPD, DMODEL, 1, 0);

    // 8. y2 = h_h @ W2 + b2 (fp32 out)
    gemm_h<<<dim3(DMODEL / 128, (QLEN * BATCH) / 128), 256, gemm_smem>>>(
        h_h, w2_h, y2, nullptr, b2, QLEN * BATCH, DMODEL, MLPD, 0, 0);

    // 9. out = LN2(x + y2)
    ln_kernel<<<QLEN * BATCH, 256>>>(x, y2, ln2_g, ln2_b, out, nullptr);
}

// round 17
// speedup vs baseline: 1.4608x; 1.4608x over previous
#include <cuda_runtime.h>
#include <cuda_fp16.h>
#include <math.h>

#define QLEN  1024
#define BATCH 4
#define DMODEL 1024
#define NH    16
#define HD    64
#define MEMLEN 512
#define KLEN  1536
#define MLPD  4096
#define QKV3  3072
#define ATT_SCALE 0.125f
#define LNEPS 1e-5f

// ---------------- scratch (static device globals; no allocation) ----------------
__device__ __half g_cat_h [(size_t)KLEN * BATCH * DMODEL];
__device__ __half g_qkv_h [(size_t)KLEN * BATCH * QKV3];
__device__ __half g_rp_h  [(size_t)KLEN * DMODEL];
__device__ __half g_BD    [(size_t)BATCH * NH * QLEN * KLEN];
__device__ __half g_ctx_h [(size_t)QLEN * BATCH * DMODEL];
__device__ float  g_y     [(size_t)QLEN * BATCH * DMODEL];
__device__ float  g_x     [(size_t)QLEN * BATCH * DMODEL];
__device__ __half g_x_h   [(size_t)QLEN * BATCH * DMODEL];
__device__ __half g_h_h   [(size_t)QLEN * BATCH * MLPD];
__device__ float  g_y2    [(size_t)QLEN * BATCH * DMODEL];
__device__ __half g_wqkv_h[(size_t)DMODEL * QKV3];
__device__ __half g_wr_h  [(size_t)DMODEL * DMODEL];
__device__ __half g_wo_h  [(size_t)DMODEL * DMODEL];
__device__ __half g_w1_h  [(size_t)DMODEL * MLPD];
__device__ __half g_w2_h  [(size_t)MLPD * DMODEL];
__device__ __half g_r_h   [(size_t)KLEN * DMODEL];

// ---------------- helpers ----------------
__device__ __forceinline__ unsigned pk(float a, float b) {
    __half2 h = __floats2half2_rn(a, b);
    return *(unsigned*)&h;
}
__device__ __forceinline__ void mma16(float c[4],
    unsigned a0, unsigned a1, unsigned a2, unsigned a3, unsigned b0, unsigned b1) {
    asm volatile(
        "mma.sync.aligned.m16n8k16.row.col.f32.f16.f16.f32 "
        "{%0,%1,%2,%3},{%4,%5,%6,%7},{%8,%9},{%0,%1,%2,%3};"
        : "+f"(c[0]), "+f"(c[1]), "+f"(c[2]), "+f"(c[3])
        : "r"(a0), "r"(a1), "r"(a2), "r"(a3), "r"(b0), "r"(b1));
}
__device__ __forceinline__ void ldm4(unsigned &r0, unsigned &r1, unsigned &r2, unsigned &r3,
                                     unsigned addr) {
    asm volatile("ldmatrix.sync.aligned.m8n8.x4.shared.b16 {%0,%1,%2,%3}, [%4];"
        : "=r"(r0), "=r"(r1), "=r"(r2), "=r"(r3) : "r"(addr));
}
__device__ __forceinline__ void ldm4t(unsigned &r0, unsigned &r1, unsigned &r2, unsigned &r3,
                                      unsigned addr) {
    asm volatile("ldmatrix.sync.aligned.m8n8.x4.trans.shared.b16 {%0,%1,%2,%3}, [%4];"
        : "=r"(r0), "=r"(r1), "=r"(r2), "=r"(r3) : "r"(addr));
}
#define CPA(dst, src) asm volatile("cp.async.cg.shared.global [%0],[%1],16;\n" :: "r"(dst), "l"(src))
#define CPC()         asm volatile("cp.async.commit_group;\n")
#define CPW(n)        asm volatile("cp.async.wait_group %0;\n" :: "n"(n))

// ---------------- fused rounding to fp16: weights + r + concat in ONE launch --------
struct Seg { const float* s; __half* d; size_t n4; };
struct Segs8 { Seg v[8]; };
__global__ void round_all(Segs8 segs) {
    #pragma unroll 1
    for (int k = 0; k < 8; k++) {
        const float* s = segs.v[k].s;
        __half* d = segs.v[k].d;
        size_t n4 = segs.v[k].n4;
        for (size_t i = (size_t)blockIdx.x * blockDim.x + threadIdx.x; i < n4;
             i += (size_t)gridDim.x * blockDim.x) {
            float4 v = ((const float4*)s)[i];
            uint2 t = { pk(v.x, v.y), pk(v.z, v.w) };
            ((uint2*)d)[i] = t;
        }
    }
}

// ---------------- 2-stage cp.async fp16 GEMM, block 128x128, BK=32 ------------------
// C = A[M,K] @ B[K,N] (+bias)(+relu); A row-major, B row-major (ldmatrix.trans)
#define GAH 40
#define GBH 136
__global__ __launch_bounds__(256, 2) void gemm_h(
    const __half* __restrict__ A, const __half* __restrict__ B,
    float* __restrict__ Cf, __half* __restrict__ Ch,
    const float* __restrict__ bias, int M, int N, int K, int relu, int qkvskip)
{
    extern __shared__ __half smh[];
    __half* As = smh;                      // [2][128*GAH]
    __half* Bs = smh + 2 * 128 * GAH;      // [2][32*GBH]
    unsigned sA = (unsigned)__cvta_generic_to_shared(As);
    unsigned sB = (unsigned)__cvta_generic_to_shared(Bs);
    int tid = threadIdx.x, lane = tid & 31, warp = tid >> 5;
    int qid = lane >> 2, qt = lane & 3;
    int l15 = lane & 15, lh = (lane >> 4) << 3;
    int wm = (warp >> 2) * 64, wn = (warp & 3) * 32;
    int m0 = blockIdx.y * 128, n0 = blockIdx.x * 128;
    if (qkvskip && (m0 + 128 <= MEMLEN * BATCH) && (n0 < DMODEL)) return;

    float c[4][4][4];
    #pragma unroll
    for (int mi = 0; mi < 4; mi++)
        #pragma unroll
        for (int ni = 0; ni < 4; ni++)
            #pragma unroll
            for (int t = 0; t < 4; t++) c[mi][ni][t] = 0.0f;

    auto stage_load = [&](int kt, int s) {
        int kb = kt << 5;
        #pragma unroll
        for (int i = 0; i < 2; i++) {               // A: 128 x 32 halves
            int id = tid + i * 256; int r = id >> 2, cc = (id & 3) * 8;
            CPA(sA + (s * 128 * GAH + r * GAH + cc) * 2, A + (size_t)(m0 + r) * K + kb + cc);
        }
        #pragma unroll
        for (int i = 0; i < 2; i++) {               // B: 32 x 128 halves
            int id = tid + i * 256; int r = id >> 4, cc = (id & 15) * 8;
            CPA(sB + (s * 32 * GBH + r * GBH + cc) * 2, B + (size_t)(kb + r) * N + n0 + cc);
        }
    };

    int KT = K >> 5;
    stage_load(0, 0); CPC();
    for (int kt = 0; kt < KT; kt++) {
        int s = kt & 1;
        if (kt + 1 < KT) stage_load(kt + 1, s ^ 1);
        CPC();
        CPW(1);
        __syncthreads();
        unsigned aoff = sA + (s * 128 * GAH) * 2;
        unsigned boff = sB + (s * 32 * GBH) * 2;
        #pragma unroll
        for (int kk = 0; kk < 2; kk++) {
            unsigned a[4][4], bf[4][2];
            #pragma unroll
            for (int mi = 0; mi < 4; mi++)
                ldm4(a[mi][0], a[mi][1], a[mi][2], a[mi][3],
                     aoff + (unsigned)(((wm + mi * 16 + l15) * GAH + kk * 16 + lh) * 2));
            #pragma unroll
            for (int nh = 0; nh < 2; nh++) {
                unsigned r0, r1, r2, r3;
                ldm4t(r0, r1, r2, r3,
                      boff + (unsigned)(((kk * 16 + l15) * GBH + wn + nh * 16 + lh) * 2));
                bf[nh * 2][0] = r0; bf[nh * 2][1] = r1;
                bf[nh * 2 + 1][0] = r2; bf[nh * 2 + 1][1] = r3;
            }
            #pragma unroll
            for (int mi = 0; mi < 4; mi++)
                #pragma unroll
                for (int ni = 0; ni < 4; ni++)
                    mma16(c[mi][ni], a[mi][0], a[mi][1], a[mi][2], a[mi][3],
                          bf[ni][0], bf[ni][1]);
        }
        __syncthreads();
    }
    #pragma unroll
    for (int mi = 0; mi < 4; mi++) {
        int row = m0 + wm + mi * 16 + qid;
        #pragma unroll
        for (int ni = 0; ni < 4; ni++) {
            int col = n0 + wn + ni * 8 + qt * 2;
            float b0 = bias ? bias[col] : 0.0f;
            float b1 = bias ? bias[col + 1] : 0.0f;
            float v00 = c[mi][ni][0] + b0, v01 = c[mi][ni][1] + b1;
            float v10 = c[mi][ni][2] + b0, v11 = c[mi][ni][3] + b1;
            if (relu) { v00 = fmaxf(v00, 0.f); v01 = fmaxf(v01, 0.f);
                        v10 = fmaxf(v10, 0.f); v11 = fmaxf(v11, 0.f); }
            if (Ch) {
                *(__half2*)(Ch + (size_t)row * N + col)       = __floats2half2_rn(v00, v01);
                *(__half2*)(Ch + (size_t)(row + 8) * N + col) = __floats2half2_rn(v10, v11);
            } else {
                Cf[(size_t)row * N + col]           = v00;
                Cf[(size_t)row * N + col + 1]       = v01;
                Cf[(size_t)(row + 8) * N + col]     = v10;
                Cf[(size_t)(row + 8) * N + col + 1] = v11;
            }
        }
    }
}

// ---------------- BD kernel: pre-shifted scaled BD (fp16, v-add fused) --------------
// Epilogue: stage S tile in smem (reusing Q/R buffers), then per-row COALESCED stores.
#define BDH 72
#define BSS 136
__global__ __launch_bounds__(256) void bd_h(
    const __half* __restrict__ qkv, const __half* __restrict__ rp,
    const float* __restrict__ vvec, __half* __restrict__ BDs)
{
    int i0 = blockIdx.y * 128, j0 = blockIdx.x * 128;
    if (j0 + i0 <= QLEN - 256) return;   // all stored j < 0: tile dead
    extern __shared__ __half smh[];
    __half* Qs = smh;                  // [128][BDH]
    __half* Rs = smh + 128 * BDH;      // [128][BDH]
    unsigned sQ = (unsigned)__cvta_generic_to_shared(Qs);
    unsigned sR = (unsigned)__cvta_generic_to_shared(Rs);
    int tid = threadIdx.x, lane = tid & 31, warp = tid >> 5;
    int qid = lane >> 2, qt = lane & 3;
    int l15 = lane & 15, lh = (lane >> 4) << 3;
    int wm = (warp >> 2) * 64, wn = (warp & 3) * 32;
    int bh = blockIdx.z, b = bh >> 4, h = bh & 15;

    #pragma unroll
    for (int i = 0; i < 4; i++) {
        int id = tid + i * 256; int r = id >> 3, cc = (id & 7) * 8;
        uint4 q = *(const uint4*)(qkv + ((size_t)(MEMLEN + i0 + r) * BATCH + b) * QKV3 + h * 64 + cc);
        __half2* qh = (__half2*)&q;
        float4 va = *(const float4*)(vvec + h * 64 + cc);
        float4 vb = *(const float4*)(vvec + h * 64 + cc + 4);
        uint4 t;
        t.x = pk(__low2float(qh[0]) + va.x, __high2float(qh[0]) + va.y);
        t.y = pk(__low2float(qh[1]) + va.z, __high2float(qh[1]) + va.w);
        t.z = pk(__low2float(qh[2]) + vb.x, __high2float(qh[2]) + vb.y);
        t.w = pk(__low2float(qh[3]) + vb.z, __high2float(qh[3]) + vb.w);
        *(uint4*)&Qs[r * BDH + cc] = t;
        *(uint4*)&Rs[r * BDH + cc] =
            *(const uint4*)(rp + (size_t)(j0 + r) * DMODEL + h * 64 + cc);
    }
    __syncthreads();
    float c[4][4][4];
    #pragma unroll
    for (int mi = 0; mi < 4; mi++)
        #pragma unroll
        for (int ni = 0; ni < 4; ni++)
            #pragma unroll
            for (int t = 0; t < 4; t++) c[mi][ni][t] = 0.0f;
    #pragma unroll
    for (int kc = 0; kc < 4; kc++) {
        unsigned a[4][4], bf[4][2];
        #pragma unroll
        for (int mi = 0; mi < 4; mi++)
            ldm4(a[mi][0], a[mi][1], a[mi][2], a[mi][3],
                 sQ + (unsigned)(((wm + mi * 16 + l15) * BDH + kc * 16 + lh) * 2));
        #pragma unroll
        for (int nh = 0; nh < 2; nh++) {
            unsigned r0, r1, r2, r3;
            ldm4(r0, r1, r2, r3,
                 sR + (unsigned)(((wn + nh * 16 + l15) * BDH + kc * 16 + lh) * 2));
            bf[nh * 2][0] = r0; bf[nh * 2][1] = r2;        // non-trans: interleaved
            bf[nh * 2 + 1][0] = r1; bf[nh * 2 + 1][1] = r3;
        }
        #pragma unroll
        for (int mi = 0; mi < 4; mi++)
            #pragma unroll
            for (int ni = 0; ni < 4; ni++)
                mma16(c[mi][ni], a[mi][0], a[mi][1], a[mi][2], a[mi][3],
                      bf[ni][0], bf[ni][1]);
    }
    // stage scaled S into smem (reuse Qs/Rs region: 128 x BSS halves = 34.8 KB <= 36.8 KB)
    __syncthreads();
    __half* Ss = smh;
    #pragma unroll
    for (int mi = 0; mi < 4; mi++) {
        #pragma unroll
        for (int half = 0; half < 2; half++) {
            int rloc = wm + mi * 16 + qid + half * 8;
            #pragma unroll
            for (int ni = 0; ni < 4; ni++) {
                int col = wn + ni * 8 + qt * 2;
                *(__half2*)&Ss[rloc * BSS + col] =
                    __floats2half2_rn(c[mi][ni][half * 2]     * ATT_SCALE,
                                      c[mi][ni][half * 2 + 1] * ATT_SCALE);
            }
        }
    }
    __syncthreads();
    // coalesced write-out: warp w owns rows [w*16, w*16+16)
    __half* bdp = BDs + (size_t)bh * QLEN * KLEN;
    #pragma unroll 1
    for (int rr = 0; rr < 16; rr++) {
        int r = warp * 16 + rr;
        int i = i0 + r;
        int jb = j0 - (QLEN - 1) + i;
        int lo = jb < 0 ? -jb : 0;
        int hi = KLEN - jb; if (hi > 128) hi = 128;
        __half* dst = bdp + (size_t)i * KLEN + jb;
        for (int cpos = lo + lane; cpos < hi; cpos += 32)
            dst[cpos] = Ss[r * BSS + cpos];
    }
}

// ---------------- fused flash attention (fp16 mma, P in registers) ------------------
// (exact R15 version — register-critical, do not perturb)
#define FH 72
__global__ __launch_bounds__(256) void flash_attn(
    const __half* __restrict__ qkv, const float* __restrict__ uvec,
    const __half* __restrict__ BDs, __half* __restrict__ ctx)
{
    extern __shared__ __half smh[];
    __half* Qs = smh;                      // [128][FH]
    __half* Ks = Qs + 128 * FH;            // [2][64][FH]
    __half* Vs = Ks + 2 * 64 * FH;         // [2][64][FH]
    unsigned sQ = (unsigned)__cvta_generic_to_shared(Qs);
    unsigned sK = (unsigned)__cvta_generic_to_shared(Ks);
    unsigned sV = (unsigned)__cvta_generic_to_shared(Vs);

    int tid = threadIdx.x, lane = tid & 31, warp = tid >> 5;
    int qid = lane >> 2, qt = lane & 3;
    int l15 = lane & 15, lh = (lane >> 4) << 3;
    int bh = blockIdx.y, b = bh >> 4, h = bh & 15;
    int i0 = blockIdx.x * 128;
    int r0w = warp * 16;

    // Q tile (u-add fused)
    #pragma unroll
    for (int i = 0; i < 4; i++) {
        int id = tid + i * 256; int r = id >> 3, cc = (id & 7) * 8;
        uint4 q = *(const uint4*)(qkv + ((size_t)(MEMLEN + i0 + r) * BATCH + b) * QKV3 + h * 64 + cc);
        __half2* qh = (__half2*)&q;
        float4 ua = *(const float4*)(uvec + h * 64 + cc);
        float4 ub = *(const float4*)(uvec + h * 64 + cc + 4);
        uint4 t;
        t.x = pk(__low2float(qh[0]) + ua.x, __high2float(qh[0]) + ua.y);
        t.y = pk(__low2float(qh[1]) + ua.z, __high2float(qh[1]) + ua.w);
        t.z = pk(__low2float(qh[2]) + ub.x, __high2float(qh[2]) + ub.y);
        t.w = pk(__low2float(qh[3]) + ub.z, __high2float(qh[3]) + ub.w);
        *(uint4*)&Qs[r * FH + cc] = t;
    }

    int njt = i0 / 64 + 10;
    if (njt > KLEN / 64) njt = KLEN / 64;

    auto stage = [&](int jt, int bf) {
        int j0 = jt * 64;
        #pragma unroll
        for (int i = 0; i < 2; i++) {
            int id = tid + i * 256; int r = id >> 3, cc = (id & 7) * 8;
            const __half* kg = qkv + ((size_t)(j0 + r) * BATCH + b) * QKV3 + DMODEL + h * 64 + cc;
            CPA(sK + ((bf * 64 + r) * FH + cc) * 2, kg);
            CPA(sV + ((bf * 64 + r) * FH + cc) * 2, kg + DMODEL);
        }
    };

    stage(0, 0); CPC();

    float m0 = -1e30f, m1 = -1e30f, l0 = 0.0f, l1 = 0.0f;
    float o[8][4];
    #pragma unroll
    for (int nt = 0; nt < 8; nt++)
        #pragma unroll
        for (int t = 0; t < 4; t++) o[nt][t] = 0.0f;

    const __half* bdp = BDs + ((size_t)bh * QLEN + i0) * KLEN;
    int irow0 = i0 + r0w + qid, irow1 = irow0 + 8;

    for (int jt = 0; jt < njt; jt++) {
        int buf = jt & 1;
        int j0 = jt * 64;
        if (jt + 1 < njt) stage(jt + 1, buf ^ 1);
        CPC();
        CPW(1);
        __syncthreads();
        unsigned sKb = sK + buf * 64 * FH * 2;
        unsigned sVb = sV + buf * 64 * FH * 2;

        // S = Q K^T
        float s[8][4];
        #pragma unroll
        for (int nt = 0; nt < 8; nt++)
            #pragma unroll
            for (int t = 0; t < 4; t++) s[nt][t] = 0.0f;
        #pragma unroll
        for (int kc = 0; kc < 4; kc++) {
            unsigned a0, a1, a2, a3;
            ldm4(a0, a1, a2, a3,
                 sQ + (unsigned)(((r0w + l15) * FH + kc * 16 + lh) * 2));
            #pragma unroll
            for (int jb = 0; jb < 4; jb++) {
                unsigned r0, r1, r2, r3;
                ldm4(r0, r1, r2, r3,
                     sKb + (unsigned)(((jb * 16 + l15) * FH + kc * 16 + lh) * 2));
                mma16(s[jb * 2],     a0, a1, a2, a3, r0, r2);
                mma16(s[jb * 2 + 1], a0, a1, a2, a3, r1, r3);
            }
        }

        // scores: scale + BD + mask; warp-local online softmax
        int msk = (j0 + 63 > i0 + MEMLEN);
        float mx0 = -1e30f, mx1 = -1e30f;
        #pragma unroll
        for (int nt = 0; nt < 8; nt++) {
            int k0 = j0 + nt * 8 + qt * 2, k1 = k0 + 1;
            float v0 = s[nt][0] * ATT_SCALE + __half2float(bdp[(size_t)(r0w + qid) * KLEN + k0]);
            float v1 = s[nt][1] * ATT_SCALE + __half2float(bdp[(size_t)(r0w + qid) * KLEN + k1]);
            float v2 = s[nt][2] * ATT_SCALE + __half2float(bdp[(size_t)(r0w + qid + 8) * KLEN + k0]);
            float v3 = s[nt][3] * ATT_SCALE + __half2float(bdp[(size_t)(r0w + qid + 8) * KLEN + k1]);
            if (msk) {
                if (k0 > irow0 + MEMLEN) v0 = -1e30f;
                if (k1 > irow0 + MEMLEN) v1 = -1e30f;
                if (k0 > irow1 + MEMLEN) v2 = -1e30f;
                if (k1 > irow1 + MEMLEN) v3 = -1e30f;
            }
            s[nt][0] = v0; s[nt][1] = v1; s[nt][2] = v2; s[nt][3] = v3;
            mx0 = fmaxf(mx0, fmaxf(v0, v1));
            mx1 = fmaxf(mx1, fmaxf(v2, v3));
        }
        mx0 = fmaxf(mx0, __shfl_xor_sync(0xffffffffu, mx0, 1));
        mx0 = fmaxf(mx0, __shfl_xor_sync(0xffffffffu, mx0, 2));
        mx1 = fmaxf(mx1, __shfl_xor_sync(0xffffffffu, mx1, 1));
        mx1 = fmaxf(mx1, __shfl_xor_sync(0xffffffffu, mx1, 2));
        float mn0 = fmaxf(m0, mx0), mn1 = fmaxf(m1, mx1);
        float al0 = __expf(m0 - mn0), al1 = __expf(m1 - mn1);
        m0 = mn0; m1 = mn1;
        #pragma unroll
        for (int nt = 0; nt < 8; nt++) {
            o[nt][0] *= al0; o[nt][1] *= al0;
            o[nt][2] *= al1; o[nt][3] *= al1;
        }
        float rs0 = 0.0f, rs1 = 0.0f;
        #pragma unroll
        for (int nt = 0; nt < 8; nt++) {
            s[nt][0] = __expf(s[nt][0] - mn0);
            s[nt][1] = __expf(s[nt][1] - mn0);
            s[nt][2] = __expf(s[nt][2] - mn1);
            s[nt][3] = __expf(s[nt][3] - mn1);
            rs0 += s[nt][0] + s[nt][1];
            rs1 += s[nt][2] + s[nt][3];
        }
        rs0 += __shfl_xor_sync(0xffffffffu, rs0, 1);
        rs0 += __shfl_xor_sync(0xffffffffu, rs0, 2);
        rs1 += __shfl_xor_sync(0xffffffffu, rs1, 1);
        rs1 += __shfl_xor_sync(0xffffffffu, rs1, 2);
        l0 = l0 * al0 + rs0;
        l1 = l1 * al1 + rs1;

        // O += P @ V   (fp16 A-frag packs directly from S C-frags: cols {2t,2t+1})
        #pragma unroll
        for (int c4 = 0; c4 < 4; c4++) {
            unsigned a0 = pk(s[2 * c4][0],     s[2 * c4][1]);
            unsigned a1 = pk(s[2 * c4][2],     s[2 * c4][3]);
            unsigned a2 = pk(s[2 * c4 + 1][0], s[2 * c4 + 1][1]);
            unsigned a3 = pk(s[2 * c4 + 1][2], s[2 * c4 + 1][3]);
            #pragma unroll
            for (int db = 0; db < 4; db++) {
                unsigned r0, r1, r2, r3;
                ldm4t(r0, r1, r2, r3,
                      sVb + (unsigned)(((c4 * 16 + l15) * FH + db * 16 + lh) * 2));
                mma16(o[db * 2],     a0, a1, a2, a3, r0, r1);
                mma16(o[db * 2 + 1], a0, a1, a2, a3, r2, r3);
            }
        }
        __syncthreads();
    }

    // epilogue: O /= l, fp16 ctx
    float inv0 = 1.0f / l0, inv1 = 1.0f / l1;
    int row0 = i0 + r0w + qid;
    #pragma unroll
    for (int nt = 0; nt < 8; nt++) {
        int col = h * 64 + nt * 8 + qt * 2;
        *(__half2*)(ctx + ((size_t)row0 * BATCH + b) * DMODEL + col) =
            __floats2half2_rn(o[nt][0] * inv0, o[nt][1] * inv0);
        *(__half2*)(ctx + ((size_t)(row0 + 8) * BATCH + b) * DMODEL + col) =
            __floats2half2_rn(o[nt][2] * inv1, o[nt][3] * inv1);
    }
}

// ---------------- layernorm: out = LN(a + b) * g + beta (+ optional fp16 copy) ------
__global__ __launch_bounds__(256) void ln_kernel(
    const float* __restrict__ a, const float* __restrict__ bres,
    const float* __restrict__ g, const float* __restrict__ beta,
    float* __restrict__ out, __half* __restrict__ out_h)
{
    int row = blockIdx.x;
    int tid = threadIdx.x;
    const float* ap = a    + (size_t)row * DMODEL;
    const float* bp = bres + (size_t)row * DMODEL;
    float x[4];
    float sum = 0.0f;
    #pragma unroll
    for (int t = 0; t < 4; t++) {
        int c = tid + t * 256;
        x[t] = ap[c] + bp[c];
        sum += x[t];
    }
    __shared__ float red[256];
    red[tid] = sum; __syncthreads();
    for (int o = 128; o > 0; o >>= 1) {
        if (tid < o) red[tid] += red[tid + o];
        __syncthreads();
    }
    float mean = red[0] * (1.0f / DMODEL); __syncthreads();
    float vs = 0.0f;
    #pragma unroll
    for (int t = 0; t < 4; t++) { float d = x[t] - mean; vs += d * d; }
    red[tid] = vs; __syncthreads();
    for (int o = 128; o > 0; o >>= 1) {
        if (tid < o) red[tid] += red[tid + o];
        __syncthreads();
    }
    float inv = rsqrtf(red[0] * (1.0f / DMODEL) + LNEPS);
    #pragma unroll
    for (int t = 0; t < 4; t++) {
        int c = tid + t * 256;
        float v = (x[t] - mean) * inv * g[c] + beta[c];
        out[(size_t)row * DMODEL + c] = v;
        if (out_h) out_h[(size_t)row * DMODEL + c] = __float2half(v);
    }
}

// ---------------- launch ----------------
extern "C" void kernel_launch(void* const* d_in, const int* in_sizes, int n_in,
                              void* d_out, int out_size)
{
    const float* inputs = (const float*)d_in[0];
    const float* r      = (const float*)d_in[1];
    const float* u      = (const float*)d_in[2];
    const float* v      = (const float*)d_in[3];
    const float* mem    = (const float*)d_in[4];
    const float* W_qkv  = (const float*)d_in[6];
    const float* W_r    = (const float*)d_in[7];
    const float* W_o    = (const float*)d_in[8];
    const float* ln1_g  = (const float*)d_in[9];
    const float* ln1_b  = (const float*)d_in[10];
    const float* ln2_g  = (const float*)d_in[11];
    const float* ln2_b  = (const float*)d_in[12];
    const float* W1     = (const float*)d_in[13];
    const float* b1     = (const float*)d_in[14];
    const float* W2     = (const float*)d_in[15];
    const float* b2     = (const float*)d_in[16];
    float* out = (float*)d_out;

    __half *cat_h, *qkv_h, *rp_h, *ctx_h, *x_h, *h_h, *BDs;
    __half *wqkv_h, *wr_h, *wo_h, *w1_h, *w2_h, *r_h;
    float *y, *x, *y2;
    cudaGetSymbolAddress((void**)&cat_h,  g_cat_h);
    cudaGetSymbolAddress((void**)&qkv_h,  g_qkv_h);
    cudaGetSymbolAddress((void**)&rp_h,   g_rp_h);
    cudaGetSymbolAddress((void**)&BDs,    g_BD);
    cudaGetSymbolAddress((void**)&ctx_h,  g_ctx_h);
    cudaGetSymbolAddress((void**)&y,      g_y);
    cudaGetSymbolAddress((void**)&x,      g_x);
    cudaGetSymbolAddress((void**)&x_h,    g_x_h);
    cudaGetSymbolAddress((void**)&h_h,    g_h_h);
    cudaGetSymbolAddress((void**)&y2,     g_y2);
    cudaGetSymbolAddress((void**)&wqkv_h, g_wqkv_h);
    cudaGetSymbolAddress((void**)&wr_h,   g_wr_h);
    cudaGetSymbolAddress((void**)&wo_h,   g_wo_h);
    cudaGetSymbolAddress((void**)&w1_h,   g_w1_h);
    cudaGetSymbolAddress((void**)&w2_h,   g_w2_h);
    cudaGetSymbolAddress((void**)&r_h,    g_r_h);

    const int gemm_smem  = (2 * 128 * GAH + 2 * 32 * GBH) * 2;
    const int bd_smem    = (2 * 128 * BDH) * 2;
    const int flash_smem = (128 * FH + 4 * 64 * FH) * 2;
    cudaFuncSetAttribute(gemm_h,     cudaFuncAttributeMaxDynamicSharedMemorySize, gemm_smem);
    cudaFuncSetAttribute(bd_h,       cudaFuncAttributeMaxDynamicSharedMemorySize, bd_smem);
    cudaFuncSetAttribute(flash_attn, cudaFuncAttributeMaxDynamicSharedMemorySize, flash_smem);

    // 0. one fused rounding launch: weights, r, and concat([mem; inputs]) -> fp16
    Segs8 segs;
    segs.v[0] = { W_qkv, wqkv_h, (size_t)DMODEL * QKV3 / 4 };
    segs.v[1] = { W1,    w1_h,   (size_t)DMODEL * MLPD / 4 };
    segs.v[2] = { W2,    w2_h,   (size_t)MLPD * DMODEL / 4 };
    segs.v[3] = { W_r,   wr_h,   (size_t)DMODEL * DMODEL / 4 };
    segs.v[4] = { W_o,   wo_h,   (size_t)DMODEL * DMODEL / 4 };
    segs.v[5] = { r,     r_h,    (size_t)KLEN * DMODEL / 4 };
    segs.v[6] = { mem,   cat_h,  (size_t)MEMLEN * BATCH * DMODEL / 4 };
    segs.v[7] = { inputs, cat_h + (size_t)MEMLEN * BATCH * DMODEL,
                  (size_t)QLEN * BATCH * DMODEL / 4 };
    round_all<<<2048, 256>>>(segs);

    // 1. qkv_h = cat_h @ W_qkv (fp16 out; Q-third skipped for mem rows)
    gemm_h<<<dim3(QKV3 / 128, (KLEN * BATCH) / 128), 256, gemm_smem>>>(
        cat_h, wqkv_h, nullptr, qkv_h, nullptr, KLEN * BATCH, QKV3, DMODEL, 0, 1);

    // 2. rp_h = r @ W_r (fp16 out)
    gemm_h<<<dim3(DMODEL / 128, KLEN / 128), 256, gemm_smem>>>(
        r_h, wr_h, nullptr, rp_h, nullptr, KLEN, DMODEL, DMODEL, 0, 0);

    // 3. BDs (pre-shifted, pre-scaled fp16; v-add fused; coalesced store)
    bd_h<<<dim3(KLEN / 128, QLEN / 128, BATCH * NH), 256, bd_smem>>>(qkv_h, rp_h, v, BDs);

    // 4. fused flash attention -> ctx_h (u-add fused)
    flash_attn<<<dim3(QLEN / 128, BATCH * NH), 256, flash_smem>>>(qkv_h, u, BDs, ctx_h);

    // 5. y = ctx_h @ W_o (fp32 out)
    gemm_h<<<dim3(DMODEL / 128, (QLEN * BATCH) / 128), 256, gemm_smem>>>(
        ctx_h, wo_h, y, nullptr, nullptr, QLEN * BATCH, DMODEL, DMODEL, 0, 0);

    // 6. x = LN1(inputs + y)  (+ fp16 copy)
    ln_kernel<<<QLEN * BATCH, 256>>>(inputs, y, ln1_g, ln1_b, x, x_h);

    // 7. h_h = relu(x_h @ W1 + b1) (fp16 out)
    gemm_h<<<dim3(MLPD / 128, (QLEN * BATCH) / 128), 256, gemm_smem>>>(
        x_h, w1_h, nullptr, h_h, b1, QLEN * BATCH, MLPD, DMODEL, 1, 0);

    // 8. y2 = h_h @ W2 + b2 (fp32 out)
    gemm_h<<<dim3(DMODEL / 128, (QLEN * BATCH) / 128), 256, gemm_smem>>>(
        h_h, w2_h, y2, nullptr, b2, QLEN * BATCH, DMODEL, MLPD, 0, 0);

    // 9. out = LN2(x + y2)
    ln_kernel<<<QLEN * BATCH, 256>>>(x, y2, ln2_g, ln2_b, out, nullptr);
}